// round 1
// baseline (speedup 1.0000x reference)
#include <cuda_runtime.h>
#include <math_constants.h>

// Problem constants
#define BB   8
#define CC   256
#define CR   128
#define TT   16
#define HH   28
#define WW   28
#define HWD  784            // 28*28
#define THW  12544          // 16*784
#define KTOP 196            // 784/4
#define NROW 1024           // B*CR
#define BN_EPS 1e-5f

// Scratch buffers (allocation-free: __device__ globals)
__device__ float g_Q [BB * CR * THW];
__device__ float g_K [BB * CR * THW];
__device__ float g_V [BB * CR * THW];
__device__ float g_Qt[NROW * TT * KTOP];
__device__ float g_Kt[NROW * TT * KTOP];
__device__ float g_Y [BB * CR * THW];

// ---------------------------------------------------------------------------
// Tiled fp32 GEMM: C_b[M,N] = A[M,K] @ B_b[K,N] (+epilogue), per-batch in grid.z
// A row-major [M,K]. B rows have stride ldb (=THW). N = THW (12544 = 196*64).
// mode 0: out = acc + bias[m]
// mode 1: out = (acc + bias[m])*scale[m] + (beta[m]-mean[m]*scale[m]) + xres
// ---------------------------------------------------------------------------
#define GBM 128
#define GBN 64
#define GBK 32
#define GTM 8
#define GTN 4

__global__ __launch_bounds__(256) void gemm_epi_kernel(
    const float* __restrict__ A,
    const float* __restrict__ Bmat,
    float* __restrict__ Cmat,
    const float* __restrict__ bias,
    const float* __restrict__ gamma,
    const float* __restrict__ beta,
    const float* __restrict__ bn_mean,
    const float* __restrict__ bn_var,
    const float* __restrict__ xres,
    int M, int K, int mode)
{
    const int ldb = THW;
    const int b   = blockIdx.z;
    const int m0  = blockIdx.x * GBM;
    const int n0  = blockIdx.y * GBN;
    const int tid = threadIdx.x;

    const float* Bb = Bmat + (long)b * K * ldb;
    float*       Cb = Cmat + (long)b * M * ldb;

    __shared__ float As[GBK][GBM + 4];   // padded vs store conflicts
    __shared__ float Bs[GBK][GBN];

    const int ty = tid >> 4;     // 0..15
    const int tx = tid & 15;     // 0..15

    float acc[GTM][GTN];
#pragma unroll
    for (int i = 0; i < GTM; i++)
#pragma unroll
        for (int j = 0; j < GTN; j++) acc[i][j] = 0.f;

    for (int kt = 0; kt < K; kt += GBK) {
        // load A tile (128x32) as float4 along K, store transposed
#pragma unroll
        for (int it = 0; it < 4; it++) {
            int f  = tid + it * 256;           // 0..1023
            int m  = f >> 3;                   // /8
            int k4 = f & 7;
            float4 v = *reinterpret_cast<const float4*>(
                &A[(long)(m0 + m) * K + kt + k4 * 4]);
            As[k4 * 4 + 0][m] = v.x;
            As[k4 * 4 + 1][m] = v.y;
            As[k4 * 4 + 2][m] = v.z;
            As[k4 * 4 + 3][m] = v.w;
        }
        // load B tile (32x64) as float4 along N
#pragma unroll
        for (int it = 0; it < 2; it++) {
            int f  = tid + it * 256;           // 0..511
            int k  = f >> 4;                   // /16
            int n4 = f & 15;
            float4 v = *reinterpret_cast<const float4*>(
                &Bb[(long)(kt + k) * ldb + n0 + n4 * 4]);
            *reinterpret_cast<float4*>(&Bs[k][n4 * 4]) = v;
        }
        __syncthreads();

#pragma unroll
        for (int kk = 0; kk < GBK; kk++) {
            float a[GTM], bv[GTN];
#pragma unroll
            for (int i = 0; i < GTM; i++) a[i] = As[kk][ty * GTM + i];
#pragma unroll
            for (int j = 0; j < GTN; j++) bv[j] = Bs[kk][tx * GTN + j];
#pragma unroll
            for (int i = 0; i < GTM; i++)
#pragma unroll
                for (int j = 0; j < GTN; j++)
                    acc[i][j] = fmaf(a[i], bv[j], acc[i][j]);
        }
        __syncthreads();
    }

    // epilogue
#pragma unroll
    for (int i = 0; i < GTM; i++) {
        int m = m0 + ty * GTM + i;
        float bi = bias[m];
        float sc = 1.f, sh = 0.f;
        if (mode == 1) {
            sc = gamma[m] * rsqrtf(bn_var[m] + BN_EPS);
            sh = beta[m] - bn_mean[m] * sc;
        }
#pragma unroll
        for (int j = 0; j < GTN; j++) {
            int n = n0 + tx * GTN + j;
            float v = acc[i][j] + bi;
            if (mode == 1) {
                v = v * sc + sh + xres[(long)b * CC * THW + (long)m * THW + n];
            }
            Cb[(long)m * THW + n] = v;
        }
    }
}

// ---------------------------------------------------------------------------
// Top-k: one block per row of length 784; bitonic sort 1024 (padded -inf),
// write first 196 (sorted descending).
// ---------------------------------------------------------------------------
__global__ __launch_bounds__(256) void topk_kernel(
    const float* __restrict__ src, float* __restrict__ dst)
{
    __shared__ float s[1024];
    const int row = blockIdx.x;
    const int tid = threadIdx.x;
    const float* r = src + (long)row * HWD;

    for (int i = tid; i < 1024; i += 256)
        s[i] = (i < HWD) ? r[i] : -CUDART_INF_F;
    __syncthreads();

    for (int k = 2; k <= 1024; k <<= 1) {
        for (int j = k >> 1; j > 0; j >>= 1) {
            for (int i = tid; i < 1024; i += 256) {
                int ixj = i ^ j;
                if (ixj > i) {
                    bool desc = ((i & k) == 0);
                    float a = s[i], c = s[ixj];
                    if ((a < c) == desc) { s[i] = c; s[ixj] = a; }
                }
            }
            __syncthreads();
        }
    }

    float* d = dst + (long)row * KTOP;
    for (int i = tid; i < KTOP; i += 256) d[i] = s[i];
}

// ---------------------------------------------------------------------------
// Attention: per n (=b*CR+cr) block:
//   corr[16,16] = Qt[16,196] @ Kt[16,196]^T ; softmax over s ; Y = attn @ V
// ---------------------------------------------------------------------------
__global__ __launch_bounds__(256) void attn_kernel(
    const float* __restrict__ Qt, const float* __restrict__ Kt,
    const float* __restrict__ V, float* __restrict__ Y)
{
    __shared__ float sQ[TT * KTOP];
    __shared__ float sK[TT * KTOP];
    __shared__ float sA[TT * TT];

    const int n   = blockIdx.x;
    const int tid = threadIdx.x;

    const float* qb = Qt + (long)n * TT * KTOP;
    const float* kb = Kt + (long)n * TT * KTOP;
    for (int i = tid; i < TT * KTOP; i += 256) { sQ[i] = qb[i]; sK[i] = kb[i]; }
    __syncthreads();

    // corr: 256 threads -> one (t,s) each
    {
        int t = tid >> 4, s = tid & 15;
        float acc = 0.f;
#pragma unroll 4
        for (int j = 0; j < KTOP; j++)
            acc = fmaf(sQ[t * KTOP + j], sK[s * KTOP + j], acc);
        sA[t * 16 + s] = acc;
    }
    __syncthreads();

    // softmax over s (16 rows handled by 16 threads)
    if (tid < TT) {
        int t = tid;
        float mx = -CUDART_INF_F;
#pragma unroll
        for (int s = 0; s < 16; s++) mx = fmaxf(mx, sA[t * 16 + s]);
        float sum = 0.f;
        float e[16];
#pragma unroll
        for (int s = 0; s < 16; s++) { e[s] = __expf(sA[t * 16 + s] - mx); sum += e[s]; }
        float inv = 1.f / sum;
#pragma unroll
        for (int s = 0; s < 16; s++) sA[t * 16 + s] = e[s] * inv;
    }
    __syncthreads();

    // Y[n, t, p] = sum_s attn[t,s] * V[n, s, p]
    const float* vb = V + (long)n * THW;
    float* yb = Y + (long)n * THW;
    for (int p = tid; p < HWD; p += 256) {
        float v[TT];
#pragma unroll
        for (int s = 0; s < TT; s++) v[s] = vb[s * HWD + p];
#pragma unroll
        for (int t = 0; t < TT; t++) {
            float acc = 0.f;
#pragma unroll
            for (int s = 0; s < TT; s++) acc = fmaf(sA[t * 16 + s], v[s], acc);
            yb[t * HWD + p] = acc;
        }
    }
}

// ---------------------------------------------------------------------------
extern "C" void kernel_launch(void* const* d_in, const int* in_sizes, int n_in,
                              void* d_out, int out_size)
{
    const float* x      = (const float*)d_in[0];
    const float* Wq     = (const float*)d_in[1];
    const float* bq     = (const float*)d_in[2];
    const float* Wk     = (const float*)d_in[3];
    const float* bk     = (const float*)d_in[4];
    const float* Wv     = (const float*)d_in[5];
    const float* bv     = (const float*)d_in[6];
    const float* Wr     = (const float*)d_in[7];
    const float* br     = (const float*)d_in[8];
    const float* gamma  = (const float*)d_in[9];
    const float* beta   = (const float*)d_in[10];
    const float* bnmean = (const float*)d_in[11];
    const float* bnvar  = (const float*)d_in[12];
    float* out = (float*)d_out;

    float *Qp, *Kp, *Vp, *Qtp, *Ktp, *Yp;
    cudaGetSymbolAddress((void**)&Qp,  g_Q);
    cudaGetSymbolAddress((void**)&Kp,  g_K);
    cudaGetSymbolAddress((void**)&Vp,  g_V);
    cudaGetSymbolAddress((void**)&Qtp, g_Qt);
    cudaGetSymbolAddress((void**)&Ktp, g_Kt);
    cudaGetSymbolAddress((void**)&Yp,  g_Y);

    dim3 gQKV(CR / GBM, THW / GBN, BB);      // (1, 196, 8)
    gemm_epi_kernel<<<gQKV, 256>>>(Wq, x, Qp, bq, nullptr, nullptr, nullptr, nullptr, nullptr, CR, CC, 0);
    gemm_epi_kernel<<<gQKV, 256>>>(Wk, x, Kp, bk, nullptr, nullptr, nullptr, nullptr, nullptr, CR, CC, 0);
    gemm_epi_kernel<<<gQKV, 256>>>(Wv, x, Vp, bv, nullptr, nullptr, nullptr, nullptr, nullptr, CR, CC, 0);

    topk_kernel<<<NROW * TT, 256>>>(Qp, Qtp);
    topk_kernel<<<NROW * TT, 256>>>(Kp, Ktp);

    attn_kernel<<<NROW, 256>>>(Qtp, Ktp, Vp, Yp);

    dim3 gRec(CC / GBM, THW / GBN, BB);      // (2, 196, 8)
    gemm_epi_kernel<<<gRec, 256>>>(Wr, Yp, out, br, gamma, beta, bnmean, bnvar, x, CC, CR, 1);
}

// round 2
// speedup vs baseline: 1.2934x; 1.2934x over previous
#include <cuda_runtime.h>
#include <math_constants.h>

// Problem constants
#define BB   8
#define CC   256
#define CR   128
#define TT   16
#define HH   28
#define WW   28
#define HWD  784            // 28*28
#define THW  12544          // 16*784
#define KTOP 196            // 784/4
#define NROW 1024           // B*CR
#define BN_EPS 1e-5f

// Scratch buffers (allocation-free: __device__ globals)
__device__ float g_Q [BB * CR * THW];
__device__ float g_K [BB * CR * THW];
__device__ float g_V [BB * CR * THW];
__device__ float g_Qt[NROW * TT * KTOP];
__device__ float g_Kt[NROW * TT * KTOP];
__device__ float g_Y [BB * CR * THW];

// ---------------------------------------------------------------------------
// Tiled fp32 GEMM: C_b[M,N] = A[M,K] @ B_b[K,N] (+epilogue), per-batch in grid.z
// ---------------------------------------------------------------------------
#define GBM 128
#define GBN 64
#define GBK 32
#define GTM 8
#define GTN 4

__global__ __launch_bounds__(256) void gemm_epi_kernel(
    const float* __restrict__ A,
    const float* __restrict__ Bmat,
    float* __restrict__ Cmat,
    const float* __restrict__ bias,
    const float* __restrict__ gamma,
    const float* __restrict__ beta,
    const float* __restrict__ bn_mean,
    const float* __restrict__ bn_var,
    const float* __restrict__ xres,
    int M, int K, int mode)
{
    const int ldb = THW;
    const int b   = blockIdx.z;
    const int m0  = blockIdx.x * GBM;
    const int n0  = blockIdx.y * GBN;
    const int tid = threadIdx.x;

    const float* Bb = Bmat + (long)b * K * ldb;
    float*       Cb = Cmat + (long)b * M * ldb;

    __shared__ float As[GBK][GBM + 4];
    __shared__ float Bs[GBK][GBN];

    const int ty = tid >> 4;
    const int tx = tid & 15;

    float acc[GTM][GTN];
#pragma unroll
    for (int i = 0; i < GTM; i++)
#pragma unroll
        for (int j = 0; j < GTN; j++) acc[i][j] = 0.f;

    for (int kt = 0; kt < K; kt += GBK) {
#pragma unroll
        for (int it = 0; it < 4; it++) {
            int f  = tid + it * 256;
            int m  = f >> 3;
            int k4 = f & 7;
            float4 v = *reinterpret_cast<const float4*>(
                &A[(long)(m0 + m) * K + kt + k4 * 4]);
            As[k4 * 4 + 0][m] = v.x;
            As[k4 * 4 + 1][m] = v.y;
            As[k4 * 4 + 2][m] = v.z;
            As[k4 * 4 + 3][m] = v.w;
        }
#pragma unroll
        for (int it = 0; it < 2; it++) {
            int f  = tid + it * 256;
            int k  = f >> 4;
            int n4 = f & 15;
            float4 v = *reinterpret_cast<const float4*>(
                &Bb[(long)(kt + k) * ldb + n0 + n4 * 4]);
            *reinterpret_cast<float4*>(&Bs[k][n4 * 4]) = v;
        }
        __syncthreads();

#pragma unroll
        for (int kk = 0; kk < GBK; kk++) {
            float a[GTM], bv[GTN];
#pragma unroll
            for (int i = 0; i < GTM; i++) a[i] = As[kk][ty * GTM + i];
#pragma unroll
            for (int j = 0; j < GTN; j++) bv[j] = Bs[kk][tx * GTN + j];
#pragma unroll
            for (int i = 0; i < GTM; i++)
#pragma unroll
                for (int j = 0; j < GTN; j++)
                    acc[i][j] = fmaf(a[i], bv[j], acc[i][j]);
        }
        __syncthreads();
    }

#pragma unroll
    for (int i = 0; i < GTM; i++) {
        int m = m0 + ty * GTM + i;
        float bi = bias[m];
        float sc = 1.f, sh = 0.f;
        if (mode == 1) {
            sc = gamma[m] * rsqrtf(bn_var[m] + BN_EPS);
            sh = beta[m] - bn_mean[m] * sc;
        }
#pragma unroll
        for (int j = 0; j < GTN; j++) {
            int n = n0 + tx * GTN + j;
            float v = acc[i][j] + bi;
            if (mode == 1) {
                v = v * sc + sh + xres[(long)b * CC * THW + (long)m * THW + n];
            }
            Cb[(long)m * THW + n] = v;
        }
    }
}

// ---------------------------------------------------------------------------
// Top-k: warp-per-row register bitonic sort of 1024 elements (784 + pad -inf).
// Layout: element idx = lane*32 + r  (r = register index 0..31).
//   j <= 16 : in-register pair compare-exchange (FMNMX only)
//   j >= 32 : shfl.bfly across lanes (jl = j>>5) + FMNMX
// Sorted DESCENDING; first 196 written out.
// ---------------------------------------------------------------------------
template<int J>
__device__ __forceinline__ void pairsDesc(float* v) {
#pragma unroll
    for (int r = 0; r < 32; r++) if (!(r & J)) {
        float a = v[r], b = v[r | J];
        v[r] = fmaxf(a, b); v[r | J] = fminf(a, b);
    }
}
template<int J>
__device__ __forceinline__ void pairsAsc(float* v) {
#pragma unroll
    for (int r = 0; r < 32; r++) if (!(r & J)) {
        float a = v[r], b = v[r | J];
        v[r] = fminf(a, b); v[r | J] = fmaxf(a, b);
    }
}
// k <= 16 stage: direction ((r & K)==0) is compile-time per pair
template<int J, int K>
__device__ __forceinline__ void stepK16(float* v) {
#pragma unroll
    for (int r = 0; r < 32; r++) if (!(r & J)) {
        float a = v[r], b = v[r | J];
        if ((r & K) == 0) { v[r] = fmaxf(a, b); v[r | J] = fminf(a, b); }
        else              { v[r] = fminf(a, b); v[r | J] = fmaxf(a, b); }
    }
}
// k >= 32 within-lane step: direction uniform per lane
template<int J>
__device__ __forceinline__ void stepWU(float* v, bool desc) {
    if (desc) pairsDesc<J>(v); else pairsAsc<J>(v);
}
// cross-lane step: takeMax uniform per lane
template<int JL>
__device__ __forceinline__ void stepX(float* v, bool takeMax) {
    if (takeMax) {
#pragma unroll
        for (int r = 0; r < 32; r++) {
            float p = __shfl_xor_sync(0xffffffffu, v[r], JL);
            v[r] = fmaxf(v[r], p);
        }
    } else {
#pragma unroll
        for (int r = 0; r < 32; r++) {
            float p = __shfl_xor_sync(0xffffffffu, v[r], JL);
            v[r] = fminf(v[r], p);
        }
    }
}
template<int JTOP>
__device__ __forceinline__ void sweepW(float* v, bool d) {
    if (JTOP >= 16) stepWU<16>(v, d);
    if (JTOP >= 8)  stepWU<8>(v, d);
    stepWU<4>(v, d); stepWU<2>(v, d); stepWU<1>(v, d);
}

__global__ __launch_bounds__(256) void topk_warp_kernel(
    const float* __restrict__ src, float* __restrict__ dst, int nrows)
{
    const int lane = threadIdx.x & 31;
    const int row  = blockIdx.x * (blockDim.x >> 5) + (threadIdx.x >> 5);
    if (row >= nrows) return;

    const float* rp = src + (size_t)row * HWD;
    float v[32];
#pragma unroll
    for (int q = 0; q < 8; q++) {
        int i0 = lane * 32 + q * 4;
        if (i0 < HWD) {
            float4 f = *reinterpret_cast<const float4*>(rp + i0);
            v[4*q+0] = f.x; v[4*q+1] = f.y; v[4*q+2] = f.z; v[4*q+3] = f.w;
        } else {
            v[4*q+0] = -CUDART_INF_F; v[4*q+1] = -CUDART_INF_F;
            v[4*q+2] = -CUDART_INF_F; v[4*q+3] = -CUDART_INF_F;
        }
    }

    // ---- bitonic sort, descending ----
    // k = 2, 4, 8, 16 (compile-time directions)
    stepK16<1,2>(v);
    stepK16<2,4>(v);  stepK16<1,4>(v);
    stepK16<4,8>(v);  stepK16<2,8>(v);  stepK16<1,8>(v);
    stepK16<8,16>(v); stepK16<4,16>(v); stepK16<2,16>(v); stepK16<1,16>(v);
    // k = 32 : desc = ((idx & 32)==0) = ((lane & 1)==0)
    { bool d = ((lane & 1) == 0); sweepW<16>(v, d); }
    // k = 64 : desc = ((lane & 2)==0)
    { bool d = ((lane & 2) == 0);
      stepX<1>(v, d == ((lane & 1) == 0));
      sweepW<16>(v, d); }
    // k = 128
    { bool d = ((lane & 4) == 0);
      stepX<2>(v, d == ((lane & 2) == 0));
      stepX<1>(v, d == ((lane & 1) == 0));
      sweepW<16>(v, d); }
    // k = 256
    { bool d = ((lane & 8) == 0);
      stepX<4>(v, d == ((lane & 4) == 0));
      stepX<2>(v, d == ((lane & 2) == 0));
      stepX<1>(v, d == ((lane & 1) == 0));
      sweepW<16>(v, d); }
    // k = 512
    { bool d = ((lane & 16) == 0);
      stepX<8>(v, d == ((lane & 8) == 0));
      stepX<4>(v, d == ((lane & 4) == 0));
      stepX<2>(v, d == ((lane & 2) == 0));
      stepX<1>(v, d == ((lane & 1) == 0));
      sweepW<16>(v, d); }
    // k = 1024 : desc = true everywhere
    { stepX<16>(v, ((lane & 16) == 0));
      stepX<8>(v,  ((lane & 8) == 0));
      stepX<4>(v,  ((lane & 4) == 0));
      stepX<2>(v,  ((lane & 2) == 0));
      stepX<1>(v,  ((lane & 1) == 0));
      sweepW<16>(v, true); }

    // write top 196 (descending)
    float* dp = dst + (size_t)row * KTOP;
#pragma unroll
    for (int q = 0; q < 8; q++) {
        int i0 = lane * 32 + q * 4;
        if (i0 < KTOP) {
            *reinterpret_cast<float4*>(dp + i0) =
                make_float4(v[4*q+0], v[4*q+1], v[4*q+2], v[4*q+3]);
        }
    }
}

// ---------------------------------------------------------------------------
// Attention: per n block: corr = Qt @ Kt^T ; softmax ; Y = attn @ V
// ---------------------------------------------------------------------------
__global__ __launch_bounds__(256) void attn_kernel(
    const float* __restrict__ Qt, const float* __restrict__ Kt,
    const float* __restrict__ V, float* __restrict__ Y)
{
    __shared__ float sQ[TT * KTOP];
    __shared__ float sK[TT * KTOP];
    __shared__ float sA[TT * TT];

    const int n   = blockIdx.x;
    const int tid = threadIdx.x;

    const float* qb = Qt + (long)n * TT * KTOP;
    const float* kb = Kt + (long)n * TT * KTOP;
    for (int i = tid; i < TT * KTOP; i += 256) { sQ[i] = qb[i]; sK[i] = kb[i]; }
    __syncthreads();

    {
        int t = tid >> 4, s = tid & 15;
        float acc = 0.f;
#pragma unroll 4
        for (int j = 0; j < KTOP; j++)
            acc = fmaf(sQ[t * KTOP + j], sK[s * KTOP + j], acc);
        sA[t * 16 + s] = acc;
    }
    __syncthreads();

    if (tid < TT) {
        int t = tid;
        float mx = -CUDART_INF_F;
#pragma unroll
        for (int s = 0; s < 16; s++) mx = fmaxf(mx, sA[t * 16 + s]);
        float sum = 0.f;
        float e[16];
#pragma unroll
        for (int s = 0; s < 16; s++) { e[s] = __expf(sA[t * 16 + s] - mx); sum += e[s]; }
        float inv = 1.f / sum;
#pragma unroll
        for (int s = 0; s < 16; s++) sA[t * 16 + s] = e[s] * inv;
    }
    __syncthreads();

    const float* vb = V + (long)n * THW;
    float* yb = Y + (long)n * THW;
    for (int p = tid; p < HWD; p += 256) {
        float v[TT];
#pragma unroll
        for (int s = 0; s < TT; s++) v[s] = vb[s * HWD + p];
#pragma unroll
        for (int t = 0; t < TT; t++) {
            float acc = 0.f;
#pragma unroll
            for (int s = 0; s < TT; s++) acc = fmaf(sA[t * 16 + s], v[s], acc);
            yb[t * HWD + p] = acc;
        }
    }
}

// ---------------------------------------------------------------------------
extern "C" void kernel_launch(void* const* d_in, const int* in_sizes, int n_in,
                              void* d_out, int out_size)
{
    const float* x      = (const float*)d_in[0];
    const float* Wq     = (const float*)d_in[1];
    const float* bq     = (const float*)d_in[2];
    const float* Wk     = (const float*)d_in[3];
    const float* bk     = (const float*)d_in[4];
    const float* Wv     = (const float*)d_in[5];
    const float* bv     = (const float*)d_in[6];
    const float* Wr     = (const float*)d_in[7];
    const float* br     = (const float*)d_in[8];
    const float* gamma  = (const float*)d_in[9];
    const float* beta   = (const float*)d_in[10];
    const float* bnmean = (const float*)d_in[11];
    const float* bnvar  = (const float*)d_in[12];
    float* out = (float*)d_out;

    float *Qp, *Kp, *Vp, *Qtp, *Ktp, *Yp;
    cudaGetSymbolAddress((void**)&Qp,  g_Q);
    cudaGetSymbolAddress((void**)&Kp,  g_K);
    cudaGetSymbolAddress((void**)&Vp,  g_V);
    cudaGetSymbolAddress((void**)&Qtp, g_Qt);
    cudaGetSymbolAddress((void**)&Ktp, g_Kt);
    cudaGetSymbolAddress((void**)&Yp,  g_Y);

    dim3 gQKV(CR / GBM, THW / GBN, BB);      // (1, 196, 8)
    gemm_epi_kernel<<<gQKV, 256>>>(Wq, x, Qp, bq, nullptr, nullptr, nullptr, nullptr, nullptr, CR, CC, 0);
    gemm_epi_kernel<<<gQKV, 256>>>(Wk, x, Kp, bk, nullptr, nullptr, nullptr, nullptr, nullptr, CR, CC, 0);
    gemm_epi_kernel<<<gQKV, 256>>>(Wv, x, Vp, bv, nullptr, nullptr, nullptr, nullptr, nullptr, CR, CC, 0);

    const int nrows = NROW * TT;             // 16384
    const int wpb = 8;                       // warps (rows) per block
    topk_warp_kernel<<<(nrows + wpb - 1) / wpb, 32 * wpb>>>(Qp, Qtp, nrows);
    topk_warp_kernel<<<(nrows + wpb - 1) / wpb, 32 * wpb>>>(Kp, Ktp, nrows);

    attn_kernel<<<NROW, 256>>>(Qtp, Ktp, Vp, Yp);

    dim3 gRec(CC / GBM, THW / GBN, BB);      // (2, 196, 8)
    gemm_epi_kernel<<<gRec, 256>>>(Wr, Yp, out, br, gamma, beta, bnmean, bnvar, x, CC, CR, 1);
}

// round 4
// speedup vs baseline: 1.9031x; 1.4714x over previous
#include <cuda_runtime.h>
#include <math_constants.h>

// Problem constants
#define BB   8
#define CC   256
#define CR   128
#define TT   16
#define HH   28
#define WW   28
#define HWD  784            // 28*28
#define THW  12544          // 16*784
#define KTOP 196            // 784/4
#define NROW 1024           // B*CR
#define BN_EPS 1e-5f

// Scratch buffers (allocation-free: __device__ globals)
__device__ float g_Q [BB * CR * THW];
__device__ float g_K [BB * CR * THW];
__device__ float g_V [BB * CR * THW];
__device__ float g_Qt[NROW * TT * KTOP];
__device__ float g_Kt[NROW * TT * KTOP];
__device__ float g_Y [BB * CR * THW];

// ---------------------------------------------------------------------------
// Tiled fp32 GEMM: C_b[M,N] = A[M,K] @ B_b[K,N] (+epilogue), per-batch in grid.z
// ---------------------------------------------------------------------------
#define GBM 128
#define GBN 64
#define GBK 32
#define GTM 8
#define GTN 4

__global__ __launch_bounds__(256) void gemm_epi_kernel(
    const float* __restrict__ A,
    const float* __restrict__ Bmat,
    float* __restrict__ Cmat,
    const float* __restrict__ bias,
    const float* __restrict__ gamma,
    const float* __restrict__ beta,
    const float* __restrict__ bn_mean,
    const float* __restrict__ bn_var,
    const float* __restrict__ xres,
    int M, int K, int mode)
{
    const int ldb = THW;
    const int b   = blockIdx.z;
    const int m0  = blockIdx.x * GBM;
    const int n0  = blockIdx.y * GBN;
    const int tid = threadIdx.x;

    const float* Bb = Bmat + (long)b * K * ldb;
    float*       Cb = Cmat + (long)b * M * ldb;

    __shared__ float As[GBK][GBM + 4];
    __shared__ float Bs[GBK][GBN];

    const int ty = tid >> 4;
    const int tx = tid & 15;

    float acc[GTM][GTN];
#pragma unroll
    for (int i = 0; i < GTM; i++)
#pragma unroll
        for (int j = 0; j < GTN; j++) acc[i][j] = 0.f;

    for (int kt = 0; kt < K; kt += GBK) {
#pragma unroll
        for (int it = 0; it < 4; it++) {
            int f  = tid + it * 256;
            int m  = f >> 3;
            int k4 = f & 7;
            float4 v = *reinterpret_cast<const float4*>(
                &A[(long)(m0 + m) * K + kt + k4 * 4]);
            As[k4 * 4 + 0][m] = v.x;
            As[k4 * 4 + 1][m] = v.y;
            As[k4 * 4 + 2][m] = v.z;
            As[k4 * 4 + 3][m] = v.w;
        }
#pragma unroll
        for (int it = 0; it < 2; it++) {
            int f  = tid + it * 256;
            int k  = f >> 4;
            int n4 = f & 15;
            float4 v = *reinterpret_cast<const float4*>(
                &Bb[(long)(kt + k) * ldb + n0 + n4 * 4]);
            *reinterpret_cast<float4*>(&Bs[k][n4 * 4]) = v;
        }
        __syncthreads();

#pragma unroll
        for (int kk = 0; kk < GBK; kk++) {
            float a[GTM], bv[GTN];
#pragma unroll
            for (int i = 0; i < GTM; i++) a[i] = As[kk][ty * GTM + i];
#pragma unroll
            for (int j = 0; j < GTN; j++) bv[j] = Bs[kk][tx * GTN + j];
#pragma unroll
            for (int i = 0; i < GTM; i++)
#pragma unroll
                for (int j = 0; j < GTN; j++)
                    acc[i][j] = fmaf(a[i], bv[j], acc[i][j]);
        }
        __syncthreads();
    }

#pragma unroll
    for (int i = 0; i < GTM; i++) {
        int m = m0 + ty * GTM + i;
        float bi = bias[m];
        float sc = 1.f, sh = 0.f;
        if (mode == 1) {
            sc = gamma[m] * rsqrtf(bn_var[m] + BN_EPS);
            sh = beta[m] - bn_mean[m] * sc;
        }
#pragma unroll
        for (int j = 0; j < GTN; j++) {
            int n = n0 + tx * GTN + j;
            float v = acc[i][j] + bi;
            if (mode == 1) {
                v = v * sc + sh + xres[(long)b * CC * THW + (long)m * THW + n];
            }
            Cb[(long)m * THW + n] = v;
        }
    }
}

// ---------------------------------------------------------------------------
// Top-k: warp-per-row register bitonic sort of 1024 elements (784 + pad -inf).
// Layout: element idx = r*32 + lane  (register-major).
//  - For stages k >= 32: direction depends only on r -> COMPILE-TIME.
//      * steps j >= 32: in-register pairs, pure fmin/fmax (no selects)
//      * steps j <  32: shfl, per-r compile-time pick of lane-low bool
//  - Stages k = 2..16: one warp-level runtime bool per step + FSEL.
// Sorted DESCENDING (idx 0 = max); first 196 written out, coalesced.
// ---------------------------------------------------------------------------

// shfl step with runtime takeMax (single bool for all registers)
template<int J>
__device__ __forceinline__ void shflStepRT(float* v, bool tm) {
#pragma unroll
    for (int r = 0; r < 32; r++) {
        float p  = __shfl_xor_sync(0xffffffffu, v[r], J);
        float mn = fminf(v[r], p), mx = fmaxf(v[r], p);
        v[r] = tm ? mx : mn;
    }
}
// shfl step where direction is compile-time per r: dir_r = ((r & KR) == 0).
// takeMax = dir_r ? loJ : !loJ  (folds to one of two precomputed bools)
template<int J, int KR>
__device__ __forceinline__ void shflStepCT(float* v, bool loJ) {
#pragma unroll
    for (int r = 0; r < 32; r++) {
        const bool tm = ((r & KR) == 0) ? true : false; // compile-time branch select
        float p  = __shfl_xor_sync(0xffffffffu, v[r], J);
        float mn = fminf(v[r], p), mx = fmaxf(v[r], p);
        // tm==true -> takeMax iff loJ ; tm==false -> takeMax iff !loJ
        v[r] = (tm ? loJ : !loJ) ? mx : mn;
    }
}
// in-register step: j>=32 -> JR=j>>5 ; direction dir_r = ((r & KR)==0), KR=k>>5
// KR=0 means "all descending" (final stage)
template<int JR, int KR>
__device__ __forceinline__ void regStep(float* v) {
#pragma unroll
    for (int r = 0; r < 32; r++) if (!(r & JR)) {
        float a = v[r], b = v[r | JR];
        if ((r & KR) == 0) { v[r] = fmaxf(a, b); v[r | JR] = fminf(a, b); }
        else               { v[r] = fminf(a, b); v[r | JR] = fmaxf(a, b); }
    }
}
// tail of a stage with KR compile-time: shfl steps j=16..1
template<int KR>
__device__ __forceinline__ void shflSweepCT(float* v, bool lo16, bool lo8,
                                            bool lo4, bool lo2, bool lo1) {
    shflStepCT<16, KR>(v, lo16);
    shflStepCT<8,  KR>(v, lo8);
    shflStepCT<4,  KR>(v, lo4);
    shflStepCT<2,  KR>(v, lo2);
    shflStepCT<1,  KR>(v, lo1);
}

__global__ __launch_bounds__(256) void topk_warp_kernel(
    const float* __restrict__ src, float* __restrict__ dst, int nrows)
{
    const int lane = threadIdx.x & 31;
    const int row  = blockIdx.x * (blockDim.x >> 5) + (threadIdx.x >> 5);
    if (row >= nrows) return;

    const float* rp = src + (size_t)row * HWD;
    float v[32];
    // idx = r*32 + lane ; valid while idx < 784 (r<24 full, r==24 lane<16)
#pragma unroll
    for (int r = 0; r < 24; r++) v[r] = rp[r * 32 + lane];
    v[24] = (lane < 16) ? rp[24 * 32 + lane] : -CUDART_INF_F;
#pragma unroll
    for (int r = 25; r < 32; r++) v[r] = -CUDART_INF_F;

    const bool lo1  = (lane & 1)  == 0;
    const bool lo2  = (lane & 2)  == 0;
    const bool lo4  = (lane & 4)  == 0;
    const bool lo8  = (lane & 8)  == 0;
    const bool lo16 = (lane & 16) == 0;

    // ---- stages k = 2..16 : runtime (warp-level bool) directions ----
    shflStepRT<1>(v, lo2 == lo1);                 // k=2
    shflStepRT<2>(v, lo4 == lo2);                 // k=4
    shflStepRT<1>(v, lo4 == lo1);
    shflStepRT<4>(v, lo8 == lo4);                 // k=8
    shflStepRT<2>(v, lo8 == lo2);
    shflStepRT<1>(v, lo8 == lo1);
    shflStepRT<8>(v, lo16 == lo8);                // k=16
    shflStepRT<4>(v, lo16 == lo4);
    shflStepRT<2>(v, lo16 == lo2);
    shflStepRT<1>(v, lo16 == lo1);

    // ---- k = 32 (dir_r = (r&1)==0) ----
    shflSweepCT<1>(v, lo16, lo8, lo4, lo2, lo1);
    // ---- k = 64 (KR=2): j=32 in-reg, then shfl sweep ----
    regStep<1, 2>(v);
    shflSweepCT<2>(v, lo16, lo8, lo4, lo2, lo1);
    // ---- k = 128 (KR=4) ----
    regStep<2, 4>(v); regStep<1, 4>(v);
    shflSweepCT<4>(v, lo16, lo8, lo4, lo2, lo1);
    // ---- k = 256 (KR=8) ----
    regStep<4, 8>(v); regStep<2, 8>(v); regStep<1, 8>(v);
    shflSweepCT<8>(v, lo16, lo8, lo4, lo2, lo1);
    // ---- k = 512 (KR=16) ----
    regStep<8, 16>(v); regStep<4, 16>(v); regStep<2, 16>(v); regStep<1, 16>(v);
    shflSweepCT<16>(v, lo16, lo8, lo4, lo2, lo1);
    // ---- k = 1024 (all descending, KR=0) ----
    regStep<16, 0>(v); regStep<8, 0>(v); regStep<4, 0>(v);
    regStep<2, 0>(v);  regStep<1, 0>(v);
    shflSweepCT<0>(v, lo16, lo8, lo4, lo2, lo1);

    // write top 196 (descending): idx 0..195 -> r<6 full, r==6 lane<4
    float* dp = dst + (size_t)row * KTOP;
#pragma unroll
    for (int r = 0; r < 6; r++) dp[r * 32 + lane] = v[r];
    if (lane < 4) dp[6 * 32 + lane] = v[6];
}

// ---------------------------------------------------------------------------
// Attention: per n block: corr = Qt @ Kt^T ; softmax ; Y = attn @ V
// ---------------------------------------------------------------------------
__global__ __launch_bounds__(256) void attn_kernel(
    const float* __restrict__ Qt, const float* __restrict__ Kt,
    const float* __restrict__ V, float* __restrict__ Y)
{
    __shared__ float sQ[TT * KTOP];
    __shared__ float sK[TT * KTOP];
    __shared__ float sA[TT * TT];

    const int n   = blockIdx.x;
    const int tid = threadIdx.x;

    const float* qb = Qt + (long)n * TT * KTOP;
    const float* kb = Kt + (long)n * TT * KTOP;
    for (int i = tid; i < TT * KTOP; i += 256) { sQ[i] = qb[i]; sK[i] = kb[i]; }
    __syncthreads();

    {
        int t = tid >> 4, s = tid & 15;
        float acc = 0.f;
#pragma unroll 4
        for (int j = 0; j < KTOP; j++)
            acc = fmaf(sQ[t * KTOP + j], sK[s * KTOP + j], acc);
        sA[t * 16 + s] = acc;
    }
    __syncthreads();

    if (tid < TT) {
        int t = tid;
        float mx = -CUDART_INF_F;
#pragma unroll
        for (int s = 0; s < 16; s++) mx = fmaxf(mx, sA[t * 16 + s]);
        float sum = 0.f;
        float e[16];
#pragma unroll
        for (int s = 0; s < 16; s++) { e[s] = __expf(sA[t * 16 + s] - mx); sum += e[s]; }
        float inv = 1.f / sum;
#pragma unroll
        for (int s = 0; s < 16; s++) sA[t * 16 + s] = e[s] * inv;
    }
    __syncthreads();

    const float* vb = V + (long)n * THW;
    float* yb = Y + (long)n * THW;
    for (int p = tid; p < HWD; p += 256) {
        float v[TT];
#pragma unroll
        for (int s = 0; s < TT; s++) v[s] = vb[s * HWD + p];
#pragma unroll
        for (int t = 0; t < TT; t++) {
            float acc = 0.f;
#pragma unroll
            for (int s = 0; s < TT; s++) acc = fmaf(sA[t * 16 + s], v[s], acc);
            yb[t * HWD + p] = acc;
        }
    }
}

// ---------------------------------------------------------------------------
extern "C" void kernel_launch(void* const* d_in, const int* in_sizes, int n_in,
                              void* d_out, int out_size)
{
    const float* x      = (const float*)d_in[0];
    const float* Wq     = (const float*)d_in[1];
    const float* bq     = (const float*)d_in[2];
    const float* Wk     = (const float*)d_in[3];
    const float* bk     = (const float*)d_in[4];
    const float* Wv     = (const float*)d_in[5];
    const float* bv     = (const float*)d_in[6];
    const float* Wr     = (const float*)d_in[7];
    const float* br     = (const float*)d_in[8];
    const float* gamma  = (const float*)d_in[9];
    const float* beta   = (const float*)d_in[10];
    const float* bnmean = (const float*)d_in[11];
    const float* bnvar  = (const float*)d_in[12];
    float* out = (float*)d_out;

    float *Qp, *Kp, *Vp, *Qtp, *Ktp, *Yp;
    cudaGetSymbolAddress((void**)&Qp,  g_Q);
    cudaGetSymbolAddress((void**)&Kp,  g_K);
    cudaGetSymbolAddress((void**)&Vp,  g_V);
    cudaGetSymbolAddress((void**)&Qtp, g_Qt);
    cudaGetSymbolAddress((void**)&Ktp, g_Kt);
    cudaGetSymbolAddress((void**)&Yp,  g_Y);

    dim3 gQKV(CR / GBM, THW / GBN, BB);      // (1, 196, 8)
    gemm_epi_kernel<<<gQKV, 256>>>(Wq, x, Qp, bq, nullptr, nullptr, nullptr, nullptr, nullptr, CR, CC, 0);
    gemm_epi_kernel<<<gQKV, 256>>>(Wk, x, Kp, bk, nullptr, nullptr, nullptr, nullptr, nullptr, CR, CC, 0);
    gemm_epi_kernel<<<gQKV, 256>>>(Wv, x, Vp, bv, nullptr, nullptr, nullptr, nullptr, nullptr, CR, CC, 0);

    const int nrows = NROW * TT;             // 16384
    const int wpb = 8;                       // warps (rows) per block
    topk_warp_kernel<<<(nrows + wpb - 1) / wpb, 32 * wpb>>>(Qp, Qtp, nrows);
    topk_warp_kernel<<<(nrows + wpb - 1) / wpb, 32 * wpb>>>(Kp, Ktp, nrows);

    attn_kernel<<<NROW, 256>>>(Qtp, Ktp, Vp, Yp);

    dim3 gRec(CC / GBM, THW / GBN, BB);      // (2, 196, 8)
    gemm_epi_kernel<<<gRec, 256>>>(Wr, Yp, out, br, gamma, beta, bnmean, bnvar, x, CC, CR, 1);
}

// round 5
// speedup vs baseline: 2.9261x; 1.5375x over previous
#include <cuda_runtime.h>
#include <math_constants.h>
#include <cstdint>

// Problem constants
#define BB   8
#define CC   256
#define CR   128
#define TT   16
#define HWD  784            // 28*28
#define THW  12544          // 16*784
#define KTOP 196            // 784/4
#define NROW 1024           // B*CR
#define BN_EPS 1e-5f

// Scratch buffers
__device__ float g_Q [BB * CR * THW];
__device__ float g_K [BB * CR * THW];
__device__ float g_V [BB * CR * THW];
__device__ float g_Qt[NROW * TT * KTOP];
__device__ float g_Kt[NROW * TT * KTOP];
__device__ float g_Y [BB * CR * THW];

__device__ __forceinline__ uint32_t f2tf32(float x) {
    uint32_t u;
    asm("cvt.rna.tf32.f32 %0, %1;" : "=r"(u) : "f"(x));
    return u;
}

// ---------------------------------------------------------------------------
// tf32 tensor-core GEMM: C_b[M,N] = A[M,K] @ B_b[K,N] (+epilogue)
// Block 128x128x32, 8 warps (4M x 2N), warp tile 32x64, mma.m16n8k8.
// mode 0: out = acc + bias[m]
// mode 1: out = (acc+bias)*scale[m] + shift[m] + xres
// ---------------------------------------------------------------------------
#define TBM 128
#define TBN 128
#define TBK 32
#define SPAD 136   // row stride: conflict-free fragment reads

__global__ __launch_bounds__(256) void gemm_tf32_kernel(
    const float* __restrict__ A,
    const float* __restrict__ Bmat,
    float* __restrict__ Cmat,
    const float* __restrict__ bias,
    const float* __restrict__ gamma,
    const float* __restrict__ beta,
    const float* __restrict__ bn_mean,
    const float* __restrict__ bn_var,
    const float* __restrict__ xres,
    int M, int K, int mode)
{
    const int b    = blockIdx.z;
    const int m0   = blockIdx.x * TBM;
    const int n0   = blockIdx.y * TBN;
    const int tid  = threadIdx.x;
    const int lane = tid & 31;
    const int wid  = tid >> 5;
    const int wm   = wid >> 1;          // 0..3  (M)
    const int wn   = wid & 1;           // 0..1  (N)

    const float* Bb = Bmat + (size_t)b * K * THW;
    float*       Cb = Cmat + (size_t)b * M * THW;

    __shared__ uint32_t As[TBK][SPAD];  // [k][m]
    __shared__ uint32_t Bs[TBK][SPAD];  // [k][n]

    float acc[2][8][4];
#pragma unroll
    for (int i = 0; i < 2; i++)
#pragma unroll
        for (int j = 0; j < 8; j++)
#pragma unroll
            for (int q = 0; q < 4; q++) acc[i][j][q] = 0.f;

    const int row = lane >> 2;          // 0..7
    const int kc  = lane & 3;           // 0..3

    for (int kt = 0; kt < K; kt += TBK) {
        // A tile 128x32 -> As[k][m] (converted to tf32)
#pragma unroll
        for (int it = 0; it < 4; it++) {
            int f  = tid + it * 256;
            int m  = f >> 3;
            int k4 = f & 7;
            float4 v = *reinterpret_cast<const float4*>(
                &A[(size_t)(m0 + m) * K + kt + k4 * 4]);
            As[k4 * 4 + 0][m] = f2tf32(v.x);
            As[k4 * 4 + 1][m] = f2tf32(v.y);
            As[k4 * 4 + 2][m] = f2tf32(v.z);
            As[k4 * 4 + 3][m] = f2tf32(v.w);
        }
        // B tile 32x128 -> Bs[k][n]
#pragma unroll
        for (int it = 0; it < 4; it++) {
            int f  = tid + it * 256;
            int k  = f >> 5;
            int n4 = f & 31;
            float4 v = *reinterpret_cast<const float4*>(
                &Bb[(size_t)(kt + k) * THW + n0 + n4 * 4]);
            Bs[k][n4 * 4 + 0] = f2tf32(v.x);
            Bs[k][n4 * 4 + 1] = f2tf32(v.y);
            Bs[k][n4 * 4 + 2] = f2tf32(v.z);
            Bs[k][n4 * 4 + 3] = f2tf32(v.w);
        }
        __syncthreads();

#pragma unroll
        for (int ks = 0; ks < 4; ks++) {
            const int kb = ks * 8;
            uint32_t af[2][4];
#pragma unroll
            for (int mt = 0; mt < 2; mt++) {
                int mr = wm * 32 + mt * 16 + row;
                af[mt][0] = As[kb + kc    ][mr];
                af[mt][1] = As[kb + kc    ][mr + 8];
                af[mt][2] = As[kb + kc + 4][mr];
                af[mt][3] = As[kb + kc + 4][mr + 8];
            }
            uint32_t bf[8][2];
#pragma unroll
            for (int nt = 0; nt < 8; nt++) {
                int nc = wn * 64 + nt * 8 + row;
                bf[nt][0] = Bs[kb + kc    ][nc];
                bf[nt][1] = Bs[kb + kc + 4][nc];
            }
#pragma unroll
            for (int mt = 0; mt < 2; mt++)
#pragma unroll
                for (int nt = 0; nt < 8; nt++) {
                    asm volatile(
                        "mma.sync.aligned.m16n8k8.row.col.f32.tf32.tf32.f32 "
                        "{%0,%1,%2,%3}, {%4,%5,%6,%7}, {%8,%9}, {%0,%1,%2,%3};"
                        : "+f"(acc[mt][nt][0]), "+f"(acc[mt][nt][1]),
                          "+f"(acc[mt][nt][2]), "+f"(acc[mt][nt][3])
                        : "r"(af[mt][0]), "r"(af[mt][1]),
                          "r"(af[mt][2]), "r"(af[mt][3]),
                          "r"(bf[nt][0]), "r"(bf[nt][1]));
                }
        }
        __syncthreads();
    }

    // Epilogue. c0:(row,col) c1:(row,col+1) c2:(row+8,col) c3:(row+8,col+1)
    const int coln = 2 * (lane & 3);
#pragma unroll
    for (int mt = 0; mt < 2; mt++) {
#pragma unroll
        for (int half = 0; half < 2; half++) {
            int m = m0 + wm * 32 + mt * 16 + row + half * 8;
            float bi = bias[m];
            float sc = 1.f, sh = 0.f;
            if (mode == 1) {
                sc = gamma[m] * rsqrtf(bn_var[m] + BN_EPS);
                sh = beta[m] - bn_mean[m] * sc;
            }
#pragma unroll
            for (int nt = 0; nt < 8; nt++) {
                int n = n0 + wn * 64 + nt * 8 + coln;
                float v0 = acc[mt][nt][half * 2 + 0] + bi;
                float v1 = acc[mt][nt][half * 2 + 1] + bi;
                if (mode == 1) {
                    const float* xr = xres + (size_t)b * CC * THW + (size_t)m * THW + n;
                    v0 = v0 * sc + sh + xr[0];
                    v1 = v1 * sc + sh + xr[1];
                }
                *reinterpret_cast<float2*>(&Cb[(size_t)m * THW + n]) =
                    make_float2(v0, v1);
            }
        }
    }
}

// ---------------------------------------------------------------------------
// Top-k: warp-per-row register bitonic sort (register-major layout) — R4 code.
// ---------------------------------------------------------------------------
template<int J>
__device__ __forceinline__ void shflStepRT(float* v, bool tm) {
#pragma unroll
    for (int r = 0; r < 32; r++) {
        float p  = __shfl_xor_sync(0xffffffffu, v[r], J);
        float mn = fminf(v[r], p), mx = fmaxf(v[r], p);
        v[r] = tm ? mx : mn;
    }
}
template<int J, int KR>
__device__ __forceinline__ void shflStepCT(float* v, bool loJ) {
#pragma unroll
    for (int r = 0; r < 32; r++) {
        const bool tm = ((r & KR) == 0) ? true : false;
        float p  = __shfl_xor_sync(0xffffffffu, v[r], J);
        float mn = fminf(v[r], p), mx = fmaxf(v[r], p);
        v[r] = (tm ? loJ : !loJ) ? mx : mn;
    }
}
template<int JR, int KR>
__device__ __forceinline__ void regStep(float* v) {
#pragma unroll
    for (int r = 0; r < 32; r++) if (!(r & JR)) {
        float a = v[r], b = v[r | JR];
        if ((r & KR) == 0) { v[r] = fmaxf(a, b); v[r | JR] = fminf(a, b); }
        else               { v[r] = fminf(a, b); v[r | JR] = fmaxf(a, b); }
    }
}
template<int KR>
__device__ __forceinline__ void shflSweepCT(float* v, bool lo16, bool lo8,
                                            bool lo4, bool lo2, bool lo1) {
    shflStepCT<16, KR>(v, lo16);
    shflStepCT<8,  KR>(v, lo8);
    shflStepCT<4,  KR>(v, lo4);
    shflStepCT<2,  KR>(v, lo2);
    shflStepCT<1,  KR>(v, lo1);
}

__global__ __launch_bounds__(256) void topk_warp_kernel(
    const float* __restrict__ src, float* __restrict__ dst, int nrows)
{
    const int lane = threadIdx.x & 31;
    const int row  = blockIdx.x * (blockDim.x >> 5) + (threadIdx.x >> 5);
    if (row >= nrows) return;

    const float* rp = src + (size_t)row * HWD;
    float v[32];
#pragma unroll
    for (int r = 0; r < 24; r++) v[r] = rp[r * 32 + lane];
    v[24] = (lane < 16) ? rp[24 * 32 + lane] : -CUDART_INF_F;
#pragma unroll
    for (int r = 25; r < 32; r++) v[r] = -CUDART_INF_F;

    const bool lo1  = (lane & 1)  == 0;
    const bool lo2  = (lane & 2)  == 0;
    const bool lo4  = (lane & 4)  == 0;
    const bool lo8  = (lane & 8)  == 0;
    const bool lo16 = (lane & 16) == 0;

    shflStepRT<1>(v, lo2 == lo1);
    shflStepRT<2>(v, lo4 == lo2);
    shflStepRT<1>(v, lo4 == lo1);
    shflStepRT<4>(v, lo8 == lo4);
    shflStepRT<2>(v, lo8 == lo2);
    shflStepRT<1>(v, lo8 == lo1);
    shflStepRT<8>(v, lo16 == lo8);
    shflStepRT<4>(v, lo16 == lo4);
    shflStepRT<2>(v, lo16 == lo2);
    shflStepRT<1>(v, lo16 == lo1);

    shflSweepCT<1>(v, lo16, lo8, lo4, lo2, lo1);
    regStep<1, 2>(v);
    shflSweepCT<2>(v, lo16, lo8, lo4, lo2, lo1);
    regStep<2, 4>(v); regStep<1, 4>(v);
    shflSweepCT<4>(v, lo16, lo8, lo4, lo2, lo1);
    regStep<4, 8>(v); regStep<2, 8>(v); regStep<1, 8>(v);
    shflSweepCT<8>(v, lo16, lo8, lo4, lo2, lo1);
    regStep<8, 16>(v); regStep<4, 16>(v); regStep<2, 16>(v); regStep<1, 16>(v);
    shflSweepCT<16>(v, lo16, lo8, lo4, lo2, lo1);
    regStep<16, 0>(v); regStep<8, 0>(v); regStep<4, 0>(v);
    regStep<2, 0>(v);  regStep<1, 0>(v);
    shflSweepCT<0>(v, lo16, lo8, lo4, lo2, lo1);

    float* dp = dst + (size_t)row * KTOP;
#pragma unroll
    for (int r = 0; r < 6; r++) dp[r * 32 + lane] = v[r];
    if (lane < 4) dp[6 * 32 + lane] = v[6];
}

// ---------------------------------------------------------------------------
// Attention: per n block: corr = Qt @ Kt^T ; softmax ; Y = attn @ V
// ---------------------------------------------------------------------------
__global__ __launch_bounds__(256) void attn_kernel(
    const float* __restrict__ Qt, const float* __restrict__ Kt,
    const float* __restrict__ V, float* __restrict__ Y)
{
    __shared__ float sQ[TT * KTOP];
    __shared__ float sK[TT * KTOP];
    __shared__ float sA[TT * TT];

    const int n   = blockIdx.x;
    const int tid = threadIdx.x;

    const float* qb = Qt + (long)n * TT * KTOP;
    const float* kb = Kt + (long)n * TT * KTOP;
    for (int i = tid; i < TT * KTOP; i += 256) { sQ[i] = qb[i]; sK[i] = kb[i]; }
    __syncthreads();

    {
        int t = tid >> 4, s = tid & 15;
        float acc = 0.f;
#pragma unroll 4
        for (int j = 0; j < KTOP; j++)
            acc = fmaf(sQ[t * KTOP + j], sK[s * KTOP + j], acc);
        sA[t * 16 + s] = acc;
    }
    __syncthreads();

    if (tid < TT) {
        int t = tid;
        float mx = -CUDART_INF_F;
#pragma unroll
        for (int s = 0; s < 16; s++) mx = fmaxf(mx, sA[t * 16 + s]);
        float sum = 0.f;
        float e[16];
#pragma unroll
        for (int s = 0; s < 16; s++) { e[s] = __expf(sA[t * 16 + s] - mx); sum += e[s]; }
        float inv = 1.f / sum;
#pragma unroll
        for (int s = 0; s < 16; s++) sA[t * 16 + s] = e[s] * inv;
    }
    __syncthreads();

    const float* vb = V + (long)n * THW;
    float* yb = Y + (long)n * THW;
    for (int p = tid; p < HWD; p += 256) {
        float v[TT];
#pragma unroll
        for (int s = 0; s < TT; s++) v[s] = vb[s * HWD + p];
#pragma unroll
        for (int t = 0; t < TT; t++) {
            float acc = 0.f;
#pragma unroll
            for (int s = 0; s < TT; s++) acc = fmaf(sA[t * 16 + s], v[s], acc);
            yb[t * HWD + p] = acc;
        }
    }
}

// ---------------------------------------------------------------------------
extern "C" void kernel_launch(void* const* d_in, const int* in_sizes, int n_in,
                              void* d_out, int out_size)
{
    const float* x      = (const float*)d_in[0];
    const float* Wq     = (const float*)d_in[1];
    const float* bq     = (const float*)d_in[2];
    const float* Wk     = (const float*)d_in[3];
    const float* bk     = (const float*)d_in[4];
    const float* Wv     = (const float*)d_in[5];
    const float* bv     = (const float*)d_in[6];
    const float* Wr     = (const float*)d_in[7];
    const float* br     = (const float*)d_in[8];
    const float* gamma  = (const float*)d_in[9];
    const float* beta   = (const float*)d_in[10];
    const float* bnmean = (const float*)d_in[11];
    const float* bnvar  = (const float*)d_in[12];
    float* out = (float*)d_out;

    float *Qp, *Kp, *Vp, *Qtp, *Ktp, *Yp;
    cudaGetSymbolAddress((void**)&Qp,  g_Q);
    cudaGetSymbolAddress((void**)&Kp,  g_K);
    cudaGetSymbolAddress((void**)&Vp,  g_V);
    cudaGetSymbolAddress((void**)&Qtp, g_Qt);
    cudaGetSymbolAddress((void**)&Ktp, g_Kt);
    cudaGetSymbolAddress((void**)&Yp,  g_Y);

    dim3 gQKV(CR / TBM, THW / TBN, BB);      // (1, 98, 8)
    gemm_tf32_kernel<<<gQKV, 256>>>(Wq, x, Qp, bq, nullptr, nullptr, nullptr, nullptr, nullptr, CR, CC, 0);
    gemm_tf32_kernel<<<gQKV, 256>>>(Wk, x, Kp, bk, nullptr, nullptr, nullptr, nullptr, nullptr, CR, CC, 0);
    gemm_tf32_kernel<<<gQKV, 256>>>(Wv, x, Vp, bv, nullptr, nullptr, nullptr, nullptr, nullptr, CR, CC, 0);

    const int nrows = NROW * TT;             // 16384
    const int wpb = 8;
    topk_warp_kernel<<<(nrows + wpb - 1) / wpb, 32 * wpb>>>(Qp, Qtp, nrows);
    topk_warp_kernel<<<(nrows + wpb - 1) / wpb, 32 * wpb>>>(Kp, Ktp, nrows);

    attn_kernel<<<NROW, 256>>>(Qtp, Ktp, Vp, Yp);

    dim3 gRec(CC / TBM, THW / TBN, BB);      // (2, 98, 8)
    gemm_tf32_kernel<<<gRec, 256>>>(Wr, Yp, out, br, gamma, beta, bnmean, bnvar, x, CC, CR, 1);
}

// round 6
// speedup vs baseline: 3.0939x; 1.0573x over previous
#include <cuda_runtime.h>
#include <math_constants.h>
#include <cstdint>

// Problem constants
#define BB   8
#define CC   256
#define CR   128
#define TT   16
#define HWD  784            // 28*28
#define THW  12544          // 16*784
#define KTOP 196            // 784/4
#define NROW 1024           // B*CR
#define BN_EPS 1e-5f

// Scratch buffers
__device__ float g_Q [BB * CR * THW];
__device__ float g_K [BB * CR * THW];
__device__ float g_V [BB * CR * THW];
__device__ float g_Qt[NROW * TT * KTOP];
__device__ float g_Kt[NROW * TT * KTOP];
__device__ float g_Y [BB * CR * THW];

__device__ __forceinline__ uint32_t f2tf32(float x) {
    uint32_t u;
    asm("cvt.rna.tf32.f32 %0, %1;" : "=r"(u) : "f"(x));
    return u;
}

// ---------------------------------------------------------------------------
// tf32 tensor-core GEMM (unchanged from R5 — known good)
// ---------------------------------------------------------------------------
#define TBM 128
#define TBN 128
#define TBK 32
#define SPAD 136

__global__ __launch_bounds__(256) void gemm_tf32_kernel(
    const float* __restrict__ A,
    const float* __restrict__ Bmat,
    float* __restrict__ Cmat,
    const float* __restrict__ bias,
    const float* __restrict__ gamma,
    const float* __restrict__ beta,
    const float* __restrict__ bn_mean,
    const float* __restrict__ bn_var,
    const float* __restrict__ xres,
    int M, int K, int mode)
{
    const int b    = blockIdx.z;
    const int m0   = blockIdx.x * TBM;
    const int n0   = blockIdx.y * TBN;
    const int tid  = threadIdx.x;
    const int lane = tid & 31;
    const int wid  = tid >> 5;
    const int wm   = wid >> 1;
    const int wn   = wid & 1;

    const float* Bb = Bmat + (size_t)b * K * THW;
    float*       Cb = Cmat + (size_t)b * M * THW;

    __shared__ uint32_t As[TBK][SPAD];
    __shared__ uint32_t Bs[TBK][SPAD];

    float acc[2][8][4];
#pragma unroll
    for (int i = 0; i < 2; i++)
#pragma unroll
        for (int j = 0; j < 8; j++)
#pragma unroll
            for (int q = 0; q < 4; q++) acc[i][j][q] = 0.f;

    const int row = lane >> 2;
    const int kc  = lane & 3;

    for (int kt = 0; kt < K; kt += TBK) {
#pragma unroll
        for (int it = 0; it < 4; it++) {
            int f  = tid + it * 256;
            int m  = f >> 3;
            int k4 = f & 7;
            float4 v = *reinterpret_cast<const float4*>(
                &A[(size_t)(m0 + m) * K + kt + k4 * 4]);
            As[k4 * 4 + 0][m] = f2tf32(v.x);
            As[k4 * 4 + 1][m] = f2tf32(v.y);
            As[k4 * 4 + 2][m] = f2tf32(v.z);
            As[k4 * 4 + 3][m] = f2tf32(v.w);
        }
#pragma unroll
        for (int it = 0; it < 4; it++) {
            int f  = tid + it * 256;
            int k  = f >> 5;
            int n4 = f & 31;
            float4 v = *reinterpret_cast<const float4*>(
                &Bb[(size_t)(kt + k) * THW + n0 + n4 * 4]);
            Bs[k][n4 * 4 + 0] = f2tf32(v.x);
            Bs[k][n4 * 4 + 1] = f2tf32(v.y);
            Bs[k][n4 * 4 + 2] = f2tf32(v.z);
            Bs[k][n4 * 4 + 3] = f2tf32(v.w);
        }
        __syncthreads();

#pragma unroll
        for (int ks = 0; ks < 4; ks++) {
            const int kb = ks * 8;
            uint32_t af[2][4];
#pragma unroll
            for (int mt = 0; mt < 2; mt++) {
                int mr = wm * 32 + mt * 16 + row;
                af[mt][0] = As[kb + kc    ][mr];
                af[mt][1] = As[kb + kc    ][mr + 8];
                af[mt][2] = As[kb + kc + 4][mr];
                af[mt][3] = As[kb + kc + 4][mr + 8];
            }
            uint32_t bf[8][2];
#pragma unroll
            for (int nt = 0; nt < 8; nt++) {
                int nc = wn * 64 + nt * 8 + row;
                bf[nt][0] = Bs[kb + kc    ][nc];
                bf[nt][1] = Bs[kb + kc + 4][nc];
            }
#pragma unroll
            for (int mt = 0; mt < 2; mt++)
#pragma unroll
                for (int nt = 0; nt < 8; nt++) {
                    asm volatile(
                        "mma.sync.aligned.m16n8k8.row.col.f32.tf32.tf32.f32 "
                        "{%0,%1,%2,%3}, {%4,%5,%6,%7}, {%8,%9}, {%0,%1,%2,%3};"
                        : "+f"(acc[mt][nt][0]), "+f"(acc[mt][nt][1]),
                          "+f"(acc[mt][nt][2]), "+f"(acc[mt][nt][3])
                        : "r"(af[mt][0]), "r"(af[mt][1]),
                          "r"(af[mt][2]), "r"(af[mt][3]),
                          "r"(bf[nt][0]), "r"(bf[nt][1]));
                }
        }
        __syncthreads();
    }

    const int coln = 2 * (lane & 3);
#pragma unroll
    for (int mt = 0; mt < 2; mt++) {
#pragma unroll
        for (int half = 0; half < 2; half++) {
            int m = m0 + wm * 32 + mt * 16 + row + half * 8;
            float bi = bias[m];
            float sc = 1.f, sh = 0.f;
            if (mode == 1) {
                sc = gamma[m] * rsqrtf(bn_var[m] + BN_EPS);
                sh = beta[m] - bn_mean[m] * sc;
            }
#pragma unroll
            for (int nt = 0; nt < 8; nt++) {
                int n = n0 + wn * 64 + nt * 8 + coln;
                float v0 = acc[mt][nt][half * 2 + 0] + bi;
                float v1 = acc[mt][nt][half * 2 + 1] + bi;
                if (mode == 1) {
                    const float* xr = xres + (size_t)b * CC * THW + (size_t)m * THW + n;
                    v0 = v0 * sc + sh + xr[0];
                    v1 = v1 * sc + sh + xr[1];
                }
                *reinterpret_cast<float2*>(&Cb[(size_t)m * THW + n]) =
                    make_float2(v0, v1);
            }
        }
    }
}

// ---------------------------------------------------------------------------
// Pruned warp top-k. Layout idx = r*32 + lane.
// Sort 256-chunks (stages k<=256, chunks alternate desc/asc automatically),
// then bitonic top-k selection: j=256 compare -> merge survivors -> j compare
// -> final 256 merge. Output: top 196 sorted descending.
// ---------------------------------------------------------------------------
template<int J>
__device__ __forceinline__ void shflStepRT(float* v, bool tm) {
#pragma unroll
    for (int r = 0; r < 32; r++) {
        float p  = __shfl_xor_sync(0xffffffffu, v[r], J);
        float mn = fminf(v[r], p), mx = fmaxf(v[r], p);
        v[r] = tm ? mx : mn;
    }
}
template<int J, int KR>
__device__ __forceinline__ void shflStepCT(float* v, bool loJ) {
#pragma unroll
    for (int r = 0; r < 32; r++) {
        const bool tm = ((r & KR) == 0) ? true : false;
        float p  = __shfl_xor_sync(0xffffffffu, v[r], J);
        float mn = fminf(v[r], p), mx = fmaxf(v[r], p);
        v[r] = (tm ? loJ : !loJ) ? mx : mn;
    }
}
template<int JR, int KR>
__device__ __forceinline__ void regStep(float* v) {
#pragma unroll
    for (int r = 0; r < 32; r++) if (!(r & JR)) {
        float a = v[r], b = v[r | JR];
        if ((r & KR) == 0) { v[r] = fmaxf(a, b); v[r | JR] = fminf(a, b); }
        else               { v[r] = fminf(a, b); v[r | JR] = fmaxf(a, b); }
    }
}
template<int KR>
__device__ __forceinline__ void shflSweepCT(float* v, bool lo16, bool lo8,
                                            bool lo4, bool lo2, bool lo1) {
    shflStepCT<16, KR>(v, lo16);
    shflStepCT<8,  KR>(v, lo8);
    shflStepCT<4,  KR>(v, lo4);
    shflStepCT<2,  KR>(v, lo2);
    shflStepCT<1,  KR>(v, lo1);
}
// M1: merge chunk0 (r0..7) to DESC and chunk2 (r16..23) to ASC, in lockstep
template<int JR>
__device__ __forceinline__ void mergeStepDual(float* v) {
#pragma unroll
    for (int q = 0; q < 8; q++) if (!(q & JR)) {
        { float a = v[q], b = v[q | JR];
          v[q] = fmaxf(a, b); v[q | JR] = fminf(a, b); }            // desc
        { float a = v[16 + q], b = v[16 + (q | JR)];
          v[16 + q] = fminf(a, b); v[16 + (q | JR)] = fmaxf(a, b); } // asc
    }
}
template<int J>
__device__ __forceinline__ void shflMergeDual(float* v, bool loJ) {
#pragma unroll
    for (int q = 0; q < 8; q++) {
        { float p = __shfl_xor_sync(0xffffffffu, v[q], J);
          float mn = fminf(v[q], p), mx = fmaxf(v[q], p);
          v[q] = loJ ? mx : mn; }                                   // desc
        { float p = __shfl_xor_sync(0xffffffffu, v[16 + q], J);
          float mn = fminf(v[16 + q], p), mx = fmaxf(v[16 + q], p);
          v[16 + q] = loJ ? mn : mx; }                              // asc
    }
}
// M2: final descending merge on r0..7
template<int JR>
__device__ __forceinline__ void mergeStepFinal(float* v) {
#pragma unroll
    for (int q = 0; q < 8; q++) if (!(q & JR)) {
        float a = v[q], b = v[q | JR];
        v[q] = fmaxf(a, b); v[q | JR] = fminf(a, b);
    }
}
template<int J>
__device__ __forceinline__ void shflFinal(float* v, bool loJ) {
#pragma unroll
    for (int q = 0; q < 8; q++) {
        float p  = __shfl_xor_sync(0xffffffffu, v[q], J);
        float mn = fminf(v[q], p), mx = fmaxf(v[q], p);
        v[q] = loJ ? mx : mn;
    }
}

__global__ __launch_bounds__(256) void topk_warp_kernel(
    const float* __restrict__ srcQ, float* __restrict__ dstQ,
    const float* __restrict__ srcK, float* __restrict__ dstK, int nrows)
{
    const int lane = threadIdx.x & 31;
    const int row  = blockIdx.x * (blockDim.x >> 5) + (threadIdx.x >> 5);
    if (row >= nrows) return;

    const float* src = blockIdx.y ? srcK : srcQ;
    float*       dst = blockIdx.y ? dstK : dstQ;

    const float* rp = src + (size_t)row * HWD;
    float v[32];
#pragma unroll
    for (int r = 0; r < 24; r++) v[r] = rp[r * 32 + lane];
    v[24] = (lane < 16) ? rp[24 * 32 + lane] : -CUDART_INF_F;
#pragma unroll
    for (int r = 25; r < 32; r++) v[r] = -CUDART_INF_F;

    const bool lo1  = (lane & 1)  == 0;
    const bool lo2  = (lane & 2)  == 0;
    const bool lo4  = (lane & 4)  == 0;
    const bool lo8  = (lane & 8)  == 0;
    const bool lo16 = (lane & 16) == 0;

    // ---- bitonic sort stages k = 2..256 (chunks of 256 end alternating desc/asc)
    shflStepRT<1>(v, lo2 == lo1);
    shflStepRT<2>(v, lo4 == lo2);
    shflStepRT<1>(v, lo4 == lo1);
    shflStepRT<4>(v, lo8 == lo4);
    shflStepRT<2>(v, lo8 == lo2);
    shflStepRT<1>(v, lo8 == lo1);
    shflStepRT<8>(v, lo16 == lo8);
    shflStepRT<4>(v, lo16 == lo4);
    shflStepRT<2>(v, lo16 == lo2);
    shflStepRT<1>(v, lo16 == lo1);

    shflSweepCT<1>(v, lo16, lo8, lo4, lo2, lo1);                 // k=32
    regStep<1, 2>(v);
    shflSweepCT<2>(v, lo16, lo8, lo4, lo2, lo1);                 // k=64
    regStep<2, 4>(v); regStep<1, 4>(v);
    shflSweepCT<4>(v, lo16, lo8, lo4, lo2, lo1);                 // k=128
    regStep<4, 8>(v); regStep<2, 8>(v); regStep<1, 8>(v);
    shflSweepCT<8>(v, lo16, lo8, lo4, lo2, lo1);                 // k=256

    // ---- S1: j=256 compare, keep top-256 of each chunk pair (max at low r)
#pragma unroll
    for (int q = 0; q < 8; q++) {
        { float a = v[q],      b = v[q + 8];
          v[q]      = fmaxf(a, b); v[q + 8]  = fminf(a, b); }
        { float a = v[16 + q], b = v[24 + q];
          v[16 + q] = fmaxf(a, b); v[24 + q] = fminf(a, b); }
    }
    // ---- M1: merge chunk0 -> desc, chunk2 -> asc
    mergeStepDual<4>(v); mergeStepDual<2>(v); mergeStepDual<1>(v);
    shflMergeDual<16>(v, lo16); shflMergeDual<8>(v, lo8);
    shflMergeDual<4>(v, lo4);   shflMergeDual<2>(v, lo2);
    shflMergeDual<1>(v, lo1);
    // ---- S2: keep top-256 overall (bitonic 512 = [desc | asc])
#pragma unroll
    for (int q = 0; q < 8; q++) v[q] = fmaxf(v[q], v[16 + q]);
    // ---- M2: final descending 256 merge
    mergeStepFinal<4>(v); mergeStepFinal<2>(v); mergeStepFinal<1>(v);
    shflFinal<16>(v, lo16); shflFinal<8>(v, lo8);
    shflFinal<4>(v, lo4);   shflFinal<2>(v, lo2);
    shflFinal<1>(v, lo1);

    // write top 196 (descending)
    float* dp = dst + (size_t)row * KTOP;
#pragma unroll
    for (int r = 0; r < 6; r++) dp[r * 32 + lane] = v[r];
    if (lane < 4) dp[6 * 32 + lane] = v[6];
}

// ---------------------------------------------------------------------------
// Attention: per n block: corr = Qt @ Kt^T ; softmax ; Y = attn @ V
// ---------------------------------------------------------------------------
__global__ __launch_bounds__(256) void attn_kernel(
    const float* __restrict__ Qt, const float* __restrict__ Kt,
    const float* __restrict__ V, float* __restrict__ Y)
{
    __shared__ float sQ[TT * KTOP];
    __shared__ float sK[TT * KTOP];
    __shared__ float sA[TT * TT];

    const int n   = blockIdx.x;
    const int tid = threadIdx.x;

    const float* qb = Qt + (long)n * TT * KTOP;
    const float* kb = Kt + (long)n * TT * KTOP;
    for (int i = tid; i < TT * KTOP; i += 256) { sQ[i] = qb[i]; sK[i] = kb[i]; }
    __syncthreads();

    {
        int t = tid >> 4, s = tid & 15;
        const float4* q4 = reinterpret_cast<const float4*>(sQ + t * KTOP);
        const float4* k4 = reinterpret_cast<const float4*>(sK + s * KTOP);
        float acc = 0.f;
#pragma unroll 7
        for (int j = 0; j < KTOP / 4; j++) {
            float4 a = q4[j], b = k4[j];
            acc = fmaf(a.x, b.x, acc);
            acc = fmaf(a.y, b.y, acc);
            acc = fmaf(a.z, b.z, acc);
            acc = fmaf(a.w, b.w, acc);
        }
        sA[t * 16 + s] = acc;
    }
    __syncthreads();

    if (tid < TT) {
        int t = tid;
        float mx = -CUDART_INF_F;
#pragma unroll
        for (int s = 0; s < 16; s++) mx = fmaxf(mx, sA[t * 16 + s]);
        float sum = 0.f;
        float e[16];
#pragma unroll
        for (int s = 0; s < 16; s++) { e[s] = __expf(sA[t * 16 + s] - mx); sum += e[s]; }
        float inv = 1.f / sum;
#pragma unroll
        for (int s = 0; s < 16; s++) sA[t * 16 + s] = e[s] * inv;
    }
    __syncthreads();

    const float* vb = V + (long)n * THW;
    float* yb = Y + (long)n * THW;
    for (int p = tid; p < HWD; p += 256) {
        float v[TT];
#pragma unroll
        for (int s = 0; s < TT; s++) v[s] = vb[s * HWD + p];
#pragma unroll
        for (int t = 0; t < TT; t++) {
            float acc = 0.f;
#pragma unroll
            for (int s = 0; s < TT; s++) acc = fmaf(sA[t * 16 + s], v[s], acc);
            yb[t * HWD + p] = acc;
        }
    }
}

// ---------------------------------------------------------------------------
extern "C" void kernel_launch(void* const* d_in, const int* in_sizes, int n_in,
                              void* d_out, int out_size)
{
    const float* x      = (const float*)d_in[0];
    const float* Wq     = (const float*)d_in[1];
    const float* bq     = (const float*)d_in[2];
    const float* Wk     = (const float*)d_in[3];
    const float* bk     = (const float*)d_in[4];
    const float* Wv     = (const float*)d_in[5];
    const float* bv     = (const float*)d_in[6];
    const float* Wr     = (const float*)d_in[7];
    const float* br     = (const float*)d_in[8];
    const float* gamma  = (const float*)d_in[9];
    const float* beta   = (const float*)d_in[10];
    const float* bnmean = (const float*)d_in[11];
    const float* bnvar  = (const float*)d_in[12];
    float* out = (float*)d_out;

    float *Qp, *Kp, *Vp, *Qtp, *Ktp, *Yp;
    cudaGetSymbolAddress((void**)&Qp,  g_Q);
    cudaGetSymbolAddress((void**)&Kp,  g_K);
    cudaGetSymbolAddress((void**)&Vp,  g_V);
    cudaGetSymbolAddress((void**)&Qtp, g_Qt);
    cudaGetSymbolAddress((void**)&Ktp, g_Kt);
    cudaGetSymbolAddress((void**)&Yp,  g_Y);

    dim3 gQKV(CR / TBM, THW / TBN, BB);      // (1, 98, 8)
    gemm_tf32_kernel<<<gQKV, 256>>>(Wq, x, Qp, bq, nullptr, nullptr, nullptr, nullptr, nullptr, CR, CC, 0);
    gemm_tf32_kernel<<<gQKV, 256>>>(Wk, x, Kp, bk, nullptr, nullptr, nullptr, nullptr, nullptr, CR, CC, 0);
    gemm_tf32_kernel<<<gQKV, 256>>>(Wv, x, Vp, bv, nullptr, nullptr, nullptr, nullptr, nullptr, CR, CC, 0);

    const int nrows = NROW * TT;             // 16384
    const int wpb = 8;
    dim3 gTK((nrows + wpb - 1) / wpb, 2);
    topk_warp_kernel<<<gTK, 32 * wpb>>>(Qp, Qtp, Kp, Ktp, nrows);

    attn_kernel<<<NROW, 256>>>(Qtp, Ktp, Vp, Yp);

    dim3 gRec(CC / TBM, THW / TBN, BB);      // (2, 98, 8)
    gemm_tf32_kernel<<<gRec, 256>>>(Wr, Yp, out, br, gamma, beta, bnmean, bnvar, x, CC, CR, 1);
}

// round 7
// speedup vs baseline: 3.2222x; 1.0415x over previous
#include <cuda_runtime.h>
#include <math_constants.h>
#include <cstdint>

// Problem constants
#define BB   8
#define CC   256
#define CR   128
#define TT   16
#define HWD  784            // 28*28
#define THW  12544          // 16*784
#define KTOP 196            // 784/4
#define NROW 1024           // B*CR
#define BN_EPS 1e-5f

// Scratch buffers
__device__ float g_Q [BB * CR * THW];
__device__ float g_K [BB * CR * THW];
__device__ float g_V [BB * CR * THW];
__device__ float g_Qt[NROW * TT * KTOP];
__device__ float g_Kt[NROW * TT * KTOP];
__device__ float g_Y [BB * CR * THW];

__device__ __forceinline__ uint32_t f2tf32(float x) {
    uint32_t u;
    asm("cvt.rna.tf32.f32 %0, %1;" : "=r"(u) : "f"(x));
    return u;
}
__device__ __forceinline__ void cpasync16(uint32_t daddr, const void* src) {
    asm volatile("cp.async.ca.shared.global [%0], [%1], 16;\n"
                 :: "r"(daddr), "l"(src));
}

// ---------------------------------------------------------------------------
// Pipelined tf32 tensor-core GEMM, 2-stage cp.async double buffering.
// Block 128x128x16, 8 warps (4M x 2N), warp tile 32x64, mma.m16n8k8.
// mode 0 (QKV): blockIdx.x in {0,1,2} selects (Wq,bq,Q)/(Wk,..)/(Wv,..); M=128,K=256
// mode 1 (rec): A=A0; m-tile = blockIdx.x; BN + residual epilogue; M=256,K=128
// ---------------------------------------------------------------------------
#define TBM 128
#define TBN 128
#define TBK 16
#define APAD 20    // As row stride (floats): row*20 mod 32 = bank permutation
#define BPAD 136   // Bs row stride (floats): k*136 -> kc*8+row perfect

__global__ __launch_bounds__(256) void gemm_tf32_pipe_kernel(
    const float* __restrict__ A0, const float* __restrict__ A1,
    const float* __restrict__ A2,
    const float* __restrict__ Bmat,
    float* __restrict__ C0, float* __restrict__ C1, float* __restrict__ C2,
    const float* __restrict__ bias0, const float* __restrict__ bias1,
    const float* __restrict__ bias2,
    const float* __restrict__ gamma,
    const float* __restrict__ beta,
    const float* __restrict__ bn_mean,
    const float* __restrict__ bn_var,
    const float* __restrict__ xres,
    int M, int K, int mode)
{
    const int b    = blockIdx.z;
    const int bx   = blockIdx.x;
    const int n0   = blockIdx.y * TBN;
    const int tid  = threadIdx.x;
    const int lane = tid & 31;
    const int wid  = tid >> 5;
    const int wm   = wid >> 1;
    const int wn   = wid & 1;

    const float* A;
    const float* bias;
    float* C;
    int m0;
    if (mode == 0) {
        A    = (bx == 0) ? A0 : (bx == 1) ? A1 : A2;
        bias = (bx == 0) ? bias0 : (bx == 1) ? bias1 : bias2;
        C    = (bx == 0) ? C0 : (bx == 1) ? C1 : C2;
        m0   = 0;
    } else {
        A = A0; bias = bias0; C = C0;
        m0 = bx * TBM;
    }

    const float* Bb = Bmat + (size_t)b * K * THW;
    float*       Cb = C    + (size_t)b * M * THW;

    __shared__ float As[2][TBM][APAD];   // [stage][m][k]
    __shared__ float Bs[2][TBK][BPAD];   // [stage][k][n]

    float acc[2][8][4];
#pragma unroll
    for (int i = 0; i < 2; i++)
#pragma unroll
        for (int j = 0; j < 8; j++)
#pragma unroll
            for (int q = 0; q < 4; q++) acc[i][j][q] = 0.f;

    const int row = lane >> 2;   // 0..7
    const int kc  = lane & 3;    // 0..3

    // cp.async index precompute
    // A tile: 128 rows x 16 floats = 512 x 16B chunks; thread does 2
    const int am0 = (tid * 2)     >> 2, ak0 = (tid * 2)     & 3;
    const int am1 = (tid * 2 + 1) >> 2, ak1 = (tid * 2 + 1) & 3;
    // B tile: 16 rows x 128 floats = 512 chunks; thread does 2
    const int bk0 = (tid * 2)     >> 5, bn0c = (tid * 2)     & 31;
    const int bk1 = (tid * 2 + 1) >> 5, bn1c = (tid * 2 + 1) & 31;

    uint32_t asBase = (uint32_t)__cvta_generic_to_shared(&As[0][0][0]);
    uint32_t bsBase = (uint32_t)__cvta_generic_to_shared(&Bs[0][0][0]);
    const uint32_t asStage = TBM * APAD * 4;
    const uint32_t bsStage = TBK * BPAD * 4;

    const int nkt = K / TBK;

    // prologue: stage 0
    {
        cpasync16(asBase + (am0 * APAD + ak0 * 4) * 4,
                  A + (size_t)(m0 + am0) * K + ak0 * 4);
        cpasync16(asBase + (am1 * APAD + ak1 * 4) * 4,
                  A + (size_t)(m0 + am1) * K + ak1 * 4);
        cpasync16(bsBase + (bk0 * BPAD + bn0c * 4) * 4,
                  Bb + (size_t)bk0 * THW + n0 + bn0c * 4);
        cpasync16(bsBase + (bk1 * BPAD + bn1c * 4) * 4,
                  Bb + (size_t)bk1 * THW + n0 + bn1c * 4);
        asm volatile("cp.async.commit_group;\n");
    }

    for (int i = 0; i < nkt; i++) {
        const int s = i & 1;
        if (i + 1 < nkt) {
            const int kt = (i + 1) * TBK;
            const uint32_t so = (s ^ 1);
            cpasync16(asBase + so * asStage + (am0 * APAD + ak0 * 4) * 4,
                      A + (size_t)(m0 + am0) * K + kt + ak0 * 4);
            cpasync16(asBase + so * asStage + (am1 * APAD + ak1 * 4) * 4,
                      A + (size_t)(m0 + am1) * K + kt + ak1 * 4);
            cpasync16(bsBase + so * bsStage + (bk0 * BPAD + bn0c * 4) * 4,
                      Bb + (size_t)(kt + bk0) * THW + n0 + bn0c * 4);
            cpasync16(bsBase + so * bsStage + (bk1 * BPAD + bn1c * 4) * 4,
                      Bb + (size_t)(kt + bk1) * THW + n0 + bn1c * 4);
            asm volatile("cp.async.commit_group;\n");
            asm volatile("cp.async.wait_group 1;\n");
        } else {
            asm volatile("cp.async.wait_group 0;\n");
        }
        __syncthreads();

#pragma unroll
        for (int ks = 0; ks < 2; ks++) {
            const int kb = ks * 8;
            uint32_t af[2][4];
#pragma unroll
            for (int mt = 0; mt < 2; mt++) {
                int mr = wm * 32 + mt * 16 + row;
                af[mt][0] = f2tf32(As[s][mr    ][kb + kc    ]);
                af[mt][1] = f2tf32(As[s][mr + 8][kb + kc    ]);
                af[mt][2] = f2tf32(As[s][mr    ][kb + kc + 4]);
                af[mt][3] = f2tf32(As[s][mr + 8][kb + kc + 4]);
            }
            uint32_t bf[8][2];
#pragma unroll
            for (int nt = 0; nt < 8; nt++) {
                int nc = wn * 64 + nt * 8 + row;
                bf[nt][0] = f2tf32(Bs[s][kb + kc    ][nc]);
                bf[nt][1] = f2tf32(Bs[s][kb + kc + 4][nc]);
            }
#pragma unroll
            for (int mt = 0; mt < 2; mt++)
#pragma unroll
                for (int nt = 0; nt < 8; nt++) {
                    asm volatile(
                        "mma.sync.aligned.m16n8k8.row.col.f32.tf32.tf32.f32 "
                        "{%0,%1,%2,%3}, {%4,%5,%6,%7}, {%8,%9}, {%0,%1,%2,%3};"
                        : "+f"(acc[mt][nt][0]), "+f"(acc[mt][nt][1]),
                          "+f"(acc[mt][nt][2]), "+f"(acc[mt][nt][3])
                        : "r"(af[mt][0]), "r"(af[mt][1]),
                          "r"(af[mt][2]), "r"(af[mt][3]),
                          "r"(bf[nt][0]), "r"(bf[nt][1]));
                }
        }
        __syncthreads();
    }

    // Epilogue. c0:(row,col) c1:(row,col+1) c2:(row+8,col) c3:(row+8,col+1)
    const int coln = 2 * (lane & 3);
#pragma unroll
    for (int mt = 0; mt < 2; mt++) {
#pragma unroll
        for (int half = 0; half < 2; half++) {
            int m = m0 + wm * 32 + mt * 16 + row + half * 8;
            float bi = bias[m];
            float sc = 1.f, sh = 0.f;
            if (mode == 1) {
                sc = gamma[m] * rsqrtf(bn_var[m] + BN_EPS);
                sh = beta[m] - bn_mean[m] * sc;
            }
#pragma unroll
            for (int nt = 0; nt < 8; nt++) {
                int n = n0 + wn * 64 + nt * 8 + coln;
                float v0 = acc[mt][nt][half * 2 + 0] + bi;
                float v1 = acc[mt][nt][half * 2 + 1] + bi;
                if (mode == 1) {
                    const float* xr = xres + (size_t)b * CC * THW + (size_t)m * THW + n;
                    v0 = v0 * sc + sh + xr[0];
                    v1 = v1 * sc + sh + xr[1];
                }
                *reinterpret_cast<float2*>(&Cb[(size_t)m * THW + n]) =
                    make_float2(v0, v1);
            }
        }
    }
}

// ---------------------------------------------------------------------------
// Pruned warp top-k (unchanged from R6 — known good)
// ---------------------------------------------------------------------------
template<int J>
__device__ __forceinline__ void shflStepRT(float* v, bool tm) {
#pragma unroll
    for (int r = 0; r < 32; r++) {
        float p  = __shfl_xor_sync(0xffffffffu, v[r], J);
        float mn = fminf(v[r], p), mx = fmaxf(v[r], p);
        v[r] = tm ? mx : mn;
    }
}
template<int J, int KR>
__device__ __forceinline__ void shflStepCT(float* v, bool loJ) {
#pragma unroll
    for (int r = 0; r < 32; r++) {
        const bool tm = ((r & KR) == 0) ? true : false;
        float p  = __shfl_xor_sync(0xffffffffu, v[r], J);
        float mn = fminf(v[r], p), mx = fmaxf(v[r], p);
        v[r] = (tm ? loJ : !loJ) ? mx : mn;
    }
}
template<int JR, int KR>
__device__ __forceinline__ void regStep(float* v) {
#pragma unroll
    for (int r = 0; r < 32; r++) if (!(r & JR)) {
        float a = v[r], b = v[r | JR];
        if ((r & KR) == 0) { v[r] = fmaxf(a, b); v[r | JR] = fminf(a, b); }
        else               { v[r] = fminf(a, b); v[r | JR] = fmaxf(a, b); }
    }
}
template<int KR>
__device__ __forceinline__ void shflSweepCT(float* v, bool lo16, bool lo8,
                                            bool lo4, bool lo2, bool lo1) {
    shflStepCT<16, KR>(v, lo16);
    shflStepCT<8,  KR>(v, lo8);
    shflStepCT<4,  KR>(v, lo4);
    shflStepCT<2,  KR>(v, lo2);
    shflStepCT<1,  KR>(v, lo1);
}
template<int JR>
__device__ __forceinline__ void mergeStepDual(float* v) {
#pragma unroll
    for (int q = 0; q < 8; q++) if (!(q & JR)) {
        { float a = v[q], b = v[q | JR];
          v[q] = fmaxf(a, b); v[q | JR] = fminf(a, b); }
        { float a = v[16 + q], b = v[16 + (q | JR)];
          v[16 + q] = fminf(a, b); v[16 + (q | JR)] = fmaxf(a, b); }
    }
}
template<int J>
__device__ __forceinline__ void shflMergeDual(float* v, bool loJ) {
#pragma unroll
    for (int q = 0; q < 8; q++) {
        { float p = __shfl_xor_sync(0xffffffffu, v[q], J);
          float mn = fminf(v[q], p), mx = fmaxf(v[q], p);
          v[q] = loJ ? mx : mn; }
        { float p = __shfl_xor_sync(0xffffffffu, v[16 + q], J);
          float mn = fminf(v[16 + q], p), mx = fmaxf(v[16 + q], p);
          v[16 + q] = loJ ? mn : mx; }
    }
}
template<int JR>
__device__ __forceinline__ void mergeStepFinal(float* v) {
#pragma unroll
    for (int q = 0; q < 8; q++) if (!(q & JR)) {
        float a = v[q], b = v[q | JR];
        v[q] = fmaxf(a, b); v[q | JR] = fminf(a, b);
    }
}
template<int J>
__device__ __forceinline__ void shflFinal(float* v, bool loJ) {
#pragma unroll
    for (int q = 0; q < 8; q++) {
        float p  = __shfl_xor_sync(0xffffffffu, v[q], J);
        float mn = fminf(v[q], p), mx = fmaxf(v[q], p);
        v[q] = loJ ? mx : mn;
    }
}

__global__ __launch_bounds__(256) void topk_warp_kernel(
    const float* __restrict__ srcQ, float* __restrict__ dstQ,
    const float* __restrict__ srcK, float* __restrict__ dstK, int nrows)
{
    const int lane = threadIdx.x & 31;
    const int row  = blockIdx.x * (blockDim.x >> 5) + (threadIdx.x >> 5);
    if (row >= nrows) return;

    const float* src = blockIdx.y ? srcK : srcQ;
    float*       dst = blockIdx.y ? dstK : dstQ;

    const float* rp = src + (size_t)row * HWD;
    float v[32];
#pragma unroll
    for (int r = 0; r < 24; r++) v[r] = rp[r * 32 + lane];
    v[24] = (lane < 16) ? rp[24 * 32 + lane] : -CUDART_INF_F;
#pragma unroll
    for (int r = 25; r < 32; r++) v[r] = -CUDART_INF_F;

    const bool lo1  = (lane & 1)  == 0;
    const bool lo2  = (lane & 2)  == 0;
    const bool lo4  = (lane & 4)  == 0;
    const bool lo8  = (lane & 8)  == 0;
    const bool lo16 = (lane & 16) == 0;

    shflStepRT<1>(v, lo2 == lo1);
    shflStepRT<2>(v, lo4 == lo2);
    shflStepRT<1>(v, lo4 == lo1);
    shflStepRT<4>(v, lo8 == lo4);
    shflStepRT<2>(v, lo8 == lo2);
    shflStepRT<1>(v, lo8 == lo1);
    shflStepRT<8>(v, lo16 == lo8);
    shflStepRT<4>(v, lo16 == lo4);
    shflStepRT<2>(v, lo16 == lo2);
    shflStepRT<1>(v, lo16 == lo1);

    shflSweepCT<1>(v, lo16, lo8, lo4, lo2, lo1);
    regStep<1, 2>(v);
    shflSweepCT<2>(v, lo16, lo8, lo4, lo2, lo1);
    regStep<2, 4>(v); regStep<1, 4>(v);
    shflSweepCT<4>(v, lo16, lo8, lo4, lo2, lo1);
    regStep<4, 8>(v); regStep<2, 8>(v); regStep<1, 8>(v);
    shflSweepCT<8>(v, lo16, lo8, lo4, lo2, lo1);

#pragma unroll
    for (int q = 0; q < 8; q++) {
        { float a = v[q],      b = v[q + 8];
          v[q]      = fmaxf(a, b); v[q + 8]  = fminf(a, b); }
        { float a = v[16 + q], b = v[24 + q];
          v[16 + q] = fmaxf(a, b); v[24 + q] = fminf(a, b); }
    }
    mergeStepDual<4>(v); mergeStepDual<2>(v); mergeStepDual<1>(v);
    shflMergeDual<16>(v, lo16); shflMergeDual<8>(v, lo8);
    shflMergeDual<4>(v, lo4);   shflMergeDual<2>(v, lo2);
    shflMergeDual<1>(v, lo1);
#pragma unroll
    for (int q = 0; q < 8; q++) v[q] = fmaxf(v[q], v[16 + q]);
    mergeStepFinal<4>(v); mergeStepFinal<2>(v); mergeStepFinal<1>(v);
    shflFinal<16>(v, lo16); shflFinal<8>(v, lo8);
    shflFinal<4>(v, lo4);   shflFinal<2>(v, lo2);
    shflFinal<1>(v, lo1);

    float* dp = dst + (size_t)row * KTOP;
#pragma unroll
    for (int r = 0; r < 6; r++) dp[r * 32 + lane] = v[r];
    if (lane < 4) dp[6 * 32 + lane] = v[6];
}

// ---------------------------------------------------------------------------
// Attention (unchanged from R6)
// ---------------------------------------------------------------------------
__global__ __launch_bounds__(256) void attn_kernel(
    const float* __restrict__ Qt, const float* __restrict__ Kt,
    const float* __restrict__ V, float* __restrict__ Y)
{
    __shared__ float sQ[TT * KTOP];
    __shared__ float sK[TT * KTOP];
    __shared__ float sA[TT * TT];

    const int n   = blockIdx.x;
    const int tid = threadIdx.x;

    const float* qb = Qt + (long)n * TT * KTOP;
    const float* kb = Kt + (long)n * TT * KTOP;
    for (int i = tid; i < TT * KTOP; i += 256) { sQ[i] = qb[i]; sK[i] = kb[i]; }
    __syncthreads();

    {
        int t = tid >> 4, s = tid & 15;
        const float4* q4 = reinterpret_cast<const float4*>(sQ + t * KTOP);
        const float4* k4 = reinterpret_cast<const float4*>(sK + s * KTOP);
        float acc = 0.f;
#pragma unroll 7
        for (int j = 0; j < KTOP / 4; j++) {
            float4 a = q4[j], b = k4[j];
            acc = fmaf(a.x, b.x, acc);
            acc = fmaf(a.y, b.y, acc);
            acc = fmaf(a.z, b.z, acc);
            acc = fmaf(a.w, b.w, acc);
        }
        sA[t * 16 + s] = acc;
    }
    __syncthreads();

    if (tid < TT) {
        int t = tid;
        float mx = -CUDART_INF_F;
#pragma unroll
        for (int s = 0; s < 16; s++) mx = fmaxf(mx, sA[t * 16 + s]);
        float sum = 0.f;
        float e[16];
#pragma unroll
        for (int s = 0; s < 16; s++) { e[s] = __expf(sA[t * 16 + s] - mx); sum += e[s]; }
        float inv = 1.f / sum;
#pragma unroll
        for (int s = 0; s < 16; s++) sA[t * 16 + s] = e[s] * inv;
    }
    __syncthreads();

    const float* vb = V + (long)n * THW;
    float* yb = Y + (long)n * THW;
    for (int p = tid; p < HWD; p += 256) {
        float v[TT];
#pragma unroll
        for (int s = 0; s < TT; s++) v[s] = vb[s * HWD + p];
#pragma unroll
        for (int t = 0; t < TT; t++) {
            float acc = 0.f;
#pragma unroll
            for (int s = 0; s < TT; s++) acc = fmaf(sA[t * 16 + s], v[s], acc);
            yb[t * HWD + p] = acc;
        }
    }
}

// ---------------------------------------------------------------------------
extern "C" void kernel_launch(void* const* d_in, const int* in_sizes, int n_in,
                              void* d_out, int out_size)
{
    const float* x      = (const float*)d_in[0];
    const float* Wq     = (const float*)d_in[1];
    const float* bq     = (const float*)d_in[2];
    const float* Wk     = (const float*)d_in[3];
    const float* bk     = (const float*)d_in[4];
    const float* Wv     = (const float*)d_in[5];
    const float* bv     = (const float*)d_in[6];
    const float* Wr     = (const float*)d_in[7];
    const float* br     = (const float*)d_in[8];
    const float* gamma  = (const float*)d_in[9];
    const float* beta   = (const float*)d_in[10];
    const float* bnmean = (const float*)d_in[11];
    const float* bnvar  = (const float*)d_in[12];
    float* out = (float*)d_out;

    float *Qp, *Kp, *Vp, *Qtp, *Ktp, *Yp;
    cudaGetSymbolAddress((void**)&Qp,  g_Q);
    cudaGetSymbolAddress((void**)&Kp,  g_K);
    cudaGetSymbolAddress((void**)&Vp,  g_V);
    cudaGetSymbolAddress((void**)&Qtp, g_Qt);
    cudaGetSymbolAddress((void**)&Ktp, g_Kt);
    cudaGetSymbolAddress((void**)&Yp,  g_Y);

    // Fused QKV: grid.x selects (W, bias, out)
    dim3 gQKV(3, THW / TBN, BB);             // (3, 98, 8)
    gemm_tf32_pipe_kernel<<<gQKV, 256>>>(
        Wq, Wk, Wv, x, Qp, Kp, Vp, bq, bk, bv,
        nullptr, nullptr, nullptr, nullptr, nullptr, CR, CC, 0);

    const int nrows = NROW * TT;             // 16384
    const int wpb = 8;
    dim3 gTK((nrows + wpb - 1) / wpb, 2);
    topk_warp_kernel<<<gTK, 32 * wpb>>>(Qp, Qtp, Kp, Ktp, nrows);

    attn_kernel<<<NROW, 256>>>(Qtp, Ktp, Vp, Yp);

    // Reconstruct: grid.x = m-tile
    dim3 gRec(CC / TBM, THW / TBN, BB);      // (2, 98, 8)
    gemm_tf32_pipe_kernel<<<gRec, 256>>>(
        Wr, nullptr, nullptr, Yp, out, nullptr, nullptr, br, nullptr, nullptr,
        gamma, beta, bnmean, bnvar, x, CC, CR, 1);
}